// round 1
// baseline (speedup 1.0000x reference)
#include <cuda_runtime.h>
#include <math.h>
#include <stdint.h>

// Problem constants
#define BB    8
#define SAQ   512
#define SBK   512
#define EDIM  1024
#define HH    16
#define DH    64
#define FFD   4096
#define LL    9
#define NTOK  (BB*SAQ)          // 4096 rows
#define WEIGHTV 5.0f
#define EPSV    1e-5f
#define ATT_SCALE 0.125f        // 1/sqrt(64)

// ---------------- scratch (device globals; no allocation allowed) ------------
__device__ float g_bufA [NTOK*EDIM];
__device__ float g_bufQ [NTOK*EDIM];
__device__ float g_bufK [NTOK*EDIM];
__device__ float g_bufV [NTOK*EDIM];
__device__ float g_bufC [NTOK*EDIM];
__device__ float g_bufO [NTOK*EDIM];
__device__ float g_bufA1[NTOK*EDIM];
__device__ float g_bufS [(size_t)BB*HH*SAQ*SBK];   // 33.5M floats
__device__ float g_bufH [(size_t)NTOK*FFD];        // 16.7M floats
__device__ float g_partials[64];                   // 32 blocks x (wce, valid)

// ---------------- SGEMM: C[M,N] = A[M,K] @ W[N,K]^T + bias[N], opt relu -----
// Requires M%128==0, N%128==0, K%16==0 (true for all calls here).
__global__ void __launch_bounds__(256, 2)
sgemm_nt_kernel(const float* __restrict__ A, const float* __restrict__ W,
                const float* __restrict__ bias, float* __restrict__ C,
                int M, int N, int K, int relu)
{
    const int bx = blockIdx.x;          // N tile
    const int by = blockIdx.y;          // M tile
    const int tid = threadIdx.x;
    const int tx = tid & 15;            // 0..15 -> cols
    const int ty = tid >> 4;            // 0..15 -> rows

    __shared__ float As[16][128];
    __shared__ float Bs[16][128];

    float acc[8][8];
#pragma unroll
    for (int i = 0; i < 8; i++)
#pragma unroll
        for (int j = 0; j < 8; j++) acc[i][j] = 0.f;

    const float* Ab = A + (size_t)(by * 128) * K;
    const float* Wb = W + (size_t)(bx * 128) * K;

    for (int kt = 0; kt < K; kt += 16) {
#pragma unroll
        for (int i = 0; i < 2; i++) {
            int f   = tid + i * 256;        // 0..511
            int row = f >> 2;               // 0..127
            int kq  = (f & 3) << 2;         // 0,4,8,12
            float4 a = *(const float4*)(Ab + (size_t)row * K + kt + kq);
            As[kq+0][row] = a.x; As[kq+1][row] = a.y;
            As[kq+2][row] = a.z; As[kq+3][row] = a.w;
            float4 b = *(const float4*)(Wb + (size_t)row * K + kt + kq);
            Bs[kq+0][row] = b.x; Bs[kq+1][row] = b.y;
            Bs[kq+2][row] = b.z; Bs[kq+3][row] = b.w;
        }
        __syncthreads();

#pragma unroll
        for (int kk = 0; kk < 16; kk++) {
            float4 a0 = *(const float4*)&As[kk][ty*4];
            float4 a1 = *(const float4*)&As[kk][64 + ty*4];
            float4 b0 = *(const float4*)&Bs[kk][tx*4];
            float4 b1 = *(const float4*)&Bs[kk][64 + tx*4];
            float av[8] = {a0.x,a0.y,a0.z,a0.w,a1.x,a1.y,a1.z,a1.w};
            float bv[8] = {b0.x,b0.y,b0.z,b0.w,b1.x,b1.y,b1.z,b1.w};
#pragma unroll
            for (int i = 0; i < 8; i++)
#pragma unroll
                for (int j = 0; j < 8; j++)
                    acc[i][j] += av[i] * bv[j];
        }
        __syncthreads();
    }

    // epilogue
#pragma unroll
    for (int ih = 0; ih < 2; ih++) {
#pragma unroll
        for (int i = 0; i < 4; i++) {
            int r = by * 128 + ih * 64 + ty * 4 + i;
            float* crow = C + (size_t)r * N + bx * 128;
#pragma unroll
            for (int jh = 0; jh < 2; jh++) {
                int c = jh * 64 + tx * 4;
                float4 bv = *(const float4*)(bias + bx * 128 + c);
                float4 v;
                v.x = acc[ih*4+i][jh*4+0] + bv.x;
                v.y = acc[ih*4+i][jh*4+1] + bv.y;
                v.z = acc[ih*4+i][jh*4+2] + bv.z;
                v.w = acc[ih*4+i][jh*4+3] + bv.w;
                if (relu) {
                    v.x = fmaxf(v.x, 0.f); v.y = fmaxf(v.y, 0.f);
                    v.z = fmaxf(v.z, 0.f); v.w = fmaxf(v.w, 0.f);
                }
                *(float4*)(crow + c) = v;
            }
        }
    }
}

// ---------------- attention scores: S[b,h,q,k] = scale * Q.Kh^T -------------
__global__ void __launch_bounds__(256)
attn_scores_kernel(const float* __restrict__ Q, const float* __restrict__ Km,
                   float* __restrict__ S)
{
    int z = blockIdx.z;                 // b*H + h
    int b = z >> 4, h = z & 15;
    const float* Qp = Q + (size_t)b * SAQ * EDIM + h * DH;
    const float* Kp = Km + (size_t)b * SBK * EDIM + h * DH;
    float* Sp = S + (size_t)z * SAQ * SBK;
    int q0 = blockIdx.y * 64, k0 = blockIdx.x * 64;
    int tid = threadIdx.x, tx = tid & 15, ty = tid >> 4;

    __shared__ float Qs[64][64];  // [d][q]
    __shared__ float Ks[64][64];  // [d][k]

#pragma unroll
    for (int i = 0; i < 4; i++) {
        int f = tid + i * 256;          // 0..1023
        int row = f >> 4;               // 0..63
        int dq  = (f & 15) << 2;        // 0..60
        float4 a = *(const float4*)(Qp + (size_t)(q0 + row) * EDIM + dq);
        Qs[dq+0][row] = a.x; Qs[dq+1][row] = a.y;
        Qs[dq+2][row] = a.z; Qs[dq+3][row] = a.w;
        float4 k = *(const float4*)(Kp + (size_t)(k0 + row) * EDIM + dq);
        Ks[dq+0][row] = k.x; Ks[dq+1][row] = k.y;
        Ks[dq+2][row] = k.z; Ks[dq+3][row] = k.w;
    }
    __syncthreads();

    float acc[4][4];
#pragma unroll
    for (int i = 0; i < 4; i++)
#pragma unroll
        for (int j = 0; j < 4; j++) acc[i][j] = 0.f;

#pragma unroll
    for (int d = 0; d < 64; d++) {
        float4 a = *(const float4*)&Qs[d][ty*4];
        float4 b = *(const float4*)&Ks[d][tx*4];
        float av[4] = {a.x,a.y,a.z,a.w};
        float bv[4] = {b.x,b.y,b.z,b.w};
#pragma unroll
        for (int i = 0; i < 4; i++)
#pragma unroll
            for (int j = 0; j < 4; j++)
                acc[i][j] += av[i] * bv[j];
    }

#pragma unroll
    for (int i = 0; i < 4; i++) {
        float4 v;
        v.x = acc[i][0] * ATT_SCALE; v.y = acc[i][1] * ATT_SCALE;
        v.z = acc[i][2] * ATT_SCALE; v.w = acc[i][3] * ATT_SCALE;
        *(float4*)(Sp + (size_t)(q0 + ty*4 + i) * SBK + k0 + tx*4) = v;
    }
}

// ---------------- row softmax over last dim (512) ---------------------------
__global__ void __launch_bounds__(128)
softmax_kernel(float* __restrict__ S)
{
    size_t row = blockIdx.x;
    float* p = S + row * SBK;
    int tid = threadIdx.x;
    __shared__ float sbuf[4];

    float4 v = ((float4*)p)[tid];
    float m = fmaxf(fmaxf(v.x, v.y), fmaxf(v.z, v.w));
#pragma unroll
    for (int o = 16; o > 0; o >>= 1) m = fmaxf(m, __shfl_xor_sync(0xffffffffu, m, o));
    if ((tid & 31) == 0) sbuf[tid >> 5] = m;
    __syncthreads();
    m = fmaxf(fmaxf(sbuf[0], sbuf[1]), fmaxf(sbuf[2], sbuf[3]));
    __syncthreads();

    float4 e;
    e.x = expf(v.x - m); e.y = expf(v.y - m);
    e.z = expf(v.z - m); e.w = expf(v.w - m);
    float s = e.x + e.y + e.z + e.w;
#pragma unroll
    for (int o = 16; o > 0; o >>= 1) s += __shfl_xor_sync(0xffffffffu, s, o);
    if ((tid & 31) == 0) sbuf[tid >> 5] = s;
    __syncthreads();
    s = sbuf[0] + sbuf[1] + sbuf[2] + sbuf[3];
    float inv = 1.0f / s;
    e.x *= inv; e.y *= inv; e.z *= inv; e.w *= inv;
    ((float4*)p)[tid] = e;
}

// ---------------- ctx[b,q,h*64+d] = sum_k P[z,q,k] * V[b,k,h*64+d] ----------
__global__ void __launch_bounds__(256)
attn_ctx_kernel(const float* __restrict__ P, const float* __restrict__ V,
                float* __restrict__ Ctx)
{
    int z = blockIdx.z;
    int b = z >> 4, h = z & 15;
    const float* Pp = P + (size_t)z * SAQ * SBK;
    const float* Vp = V + (size_t)b * SBK * EDIM + h * DH;
    float* Cp = Ctx + (size_t)b * SAQ * EDIM + h * DH;
    int q0 = blockIdx.y * 64;
    int tid = threadIdx.x, tx = tid & 15, ty = tid >> 4;

    __shared__ float Ps[32][64];  // [k][q]
    __shared__ float Vs[32][64];  // [k][d]

    float acc[4][4];
#pragma unroll
    for (int i = 0; i < 4; i++)
#pragma unroll
        for (int j = 0; j < 4; j++) acc[i][j] = 0.f;

    for (int kt = 0; kt < SBK; kt += 32) {
#pragma unroll
        for (int i = 0; i < 2; i++) {
            int f = tid + i * 256;        // 0..511
            {   // P tile: 64 q rows x 32 k cols
                int row = f >> 3;         // 0..63
                int kq  = (f & 7) << 2;   // 0..28
                float4 p = *(const float4*)(Pp + (size_t)(q0 + row) * SBK + kt + kq);
                Ps[kq+0][row] = p.x; Ps[kq+1][row] = p.y;
                Ps[kq+2][row] = p.z; Ps[kq+3][row] = p.w;
            }
            {   // V tile: 32 k rows x 64 d cols
                int row = f >> 4;         // 0..31
                int dq  = (f & 15) << 2;  // 0..60
                float4 vv = *(const float4*)(Vp + (size_t)(kt + row) * EDIM + dq);
                *(float4*)&Vs[row][dq] = vv;
            }
        }
        __syncthreads();

#pragma unroll
        for (int kk = 0; kk < 32; kk++) {
            float4 a = *(const float4*)&Ps[kk][ty*4];
            float4 b2 = *(const float4*)&Vs[kk][tx*4];
            float av[4] = {a.x,a.y,a.z,a.w};
            float bv[4] = {b2.x,b2.y,b2.z,b2.w};
#pragma unroll
            for (int i = 0; i < 4; i++)
#pragma unroll
                for (int j = 0; j < 4; j++)
                    acc[i][j] += av[i] * bv[j];
        }
        __syncthreads();
    }

#pragma unroll
    for (int i = 0; i < 4; i++) {
        float4 v;
        v.x = acc[i][0]; v.y = acc[i][1]; v.z = acc[i][2]; v.w = acc[i][3];
        *(float4*)(Cp + (size_t)(q0 + ty*4 + i) * EDIM + tx*4) = v;
    }
}

// ---------------- LayerNorm(residual): Y = LN(X + R) * g + b ----------------
__global__ void __launch_bounds__(256)
ln_residual_kernel(const float* __restrict__ X, const float* __restrict__ R,
                   const float* __restrict__ g, const float* __restrict__ bta,
                   float* __restrict__ Y)
{
    int row = blockIdx.x;
    int tid = threadIdx.x;                // 256 threads, 4 floats each
    __shared__ float sbuf[8];

    float4 x = ((const float4*)(X + (size_t)row * EDIM))[tid];
    float4 r = ((const float4*)(R + (size_t)row * EDIM))[tid];
    float4 v;
    v.x = x.x + r.x; v.y = x.y + r.y; v.z = x.z + r.z; v.w = x.w + r.w;

    float s = v.x + v.y + v.z + v.w;
#pragma unroll
    for (int o = 16; o > 0; o >>= 1) s += __shfl_xor_sync(0xffffffffu, s, o);
    if ((tid & 31) == 0) sbuf[tid >> 5] = s;
    __syncthreads();
    if (tid < 32) {
        float t = (tid < 8) ? sbuf[tid] : 0.f;
#pragma unroll
        for (int o = 4; o > 0; o >>= 1) t += __shfl_xor_sync(0xffffffffu, t, o);
        if (tid == 0) sbuf[0] = t;
    }
    __syncthreads();
    float mean = sbuf[0] * (1.0f / EDIM);
    __syncthreads();

    float4 d;
    d.x = v.x - mean; d.y = v.y - mean; d.z = v.z - mean; d.w = v.w - mean;
    float sq = d.x*d.x + d.y*d.y + d.z*d.z + d.w*d.w;
#pragma unroll
    for (int o = 16; o > 0; o >>= 1) sq += __shfl_xor_sync(0xffffffffu, sq, o);
    if ((tid & 31) == 0) sbuf[tid >> 5] = sq;
    __syncthreads();
    if (tid < 32) {
        float t = (tid < 8) ? sbuf[tid] : 0.f;
#pragma unroll
        for (int o = 4; o > 0; o >>= 1) t += __shfl_xor_sync(0xffffffffu, t, o);
        if (tid == 0) sbuf[0] = t;
    }
    __syncthreads();
    float var = sbuf[0] * (1.0f / EDIM);
    float inv = rsqrtf(var + EPSV);

    float4 gg = ((const float4*)g)[tid];
    float4 bb = ((const float4*)bta)[tid];
    float4 o4;
    o4.x = d.x * inv * gg.x + bb.x;
    o4.y = d.y * inv * gg.y + bb.y;
    o4.z = d.z * inv * gg.z + bb.z;
    o4.w = d.w * inv * gg.w + bb.w;
    ((float4*)(Y + (size_t)row * EDIM))[tid] = o4;
}

// ---------------- classifier + per-row loss + predicted labels --------------
__global__ void __launch_bounds__(128)
cls_kernel(const float* __restrict__ A, const float* __restrict__ cw,
           const float* __restrict__ cb, const int* __restrict__ mask,
           const int* __restrict__ cand, const int* __restrict__ labels,
           float* __restrict__ out_lab_f, int* __restrict__ out_lab_i,
           int write_float, float* __restrict__ partials)
{
    __shared__ float w0[EDIM];
    __shared__ float w1[EDIM];
    __shared__ float red[128];
    int tid = threadIdx.x;
#pragma unroll
    for (int i = 0; i < EDIM / 128; i++) {
        w0[tid + i * 128] = cw[tid + i * 128];
        w1[tid + i * 128] = cw[EDIM + tid + i * 128];
    }
    __syncthreads();

    int row = blockIdx.x * 128 + tid;     // 0..4095
    const float* a = A + (size_t)row * EDIM;
    float e0 = cb[0], e1 = cb[1];
#pragma unroll 4
    for (int i = 0; i < EDIM; i += 4) {
        float4 av = *(const float4*)(a + i);
        e0 += av.x * w0[i] + av.y * w0[i+1] + av.z * w0[i+2] + av.w * w0[i+3];
        e1 += av.x * w1[i] + av.y * w1[i+1] + av.z * w1[i+2] + av.w * w1[i+3];
    }
    int lab = labels[row];
    float m = fmaxf(e0, e1);
    float lse = m + logf(expf(e0 - m) + expf(e1 - m));
    float logp = ((lab == 1) ? e1 : e0) - lse;
    float ce = -logp;
    float w = (lab == 1) ? WEIGHTV : 1.0f;
    float valid = (mask[row] == 1) ? 1.0f : 0.0f;
    float contrib = ce * w * valid;

    int pred = (e1 > e0) ? 1 : 0;        // jnp.argmax: ties -> 0
    int pl = (cand[row] == 1 && pred == 1) ? 1 : 0;
    if (write_float) out_lab_f[row] = (float)pl;
    else             out_lab_i[row] = pl;

    // deterministic block reduce of (contrib, valid)
    red[tid] = contrib;
    __syncthreads();
    for (int o = 64; o > 0; o >>= 1) {
        if (tid < o) red[tid] += red[tid + o];
        __syncthreads();
    }
    if (tid == 0) partials[2 * blockIdx.x] = red[0];
    __syncthreads();
    red[tid] = valid;
    __syncthreads();
    for (int o = 64; o > 0; o >>= 1) {
        if (tid < o) red[tid] += red[tid + o];
        __syncthreads();
    }
    if (tid == 0) partials[2 * blockIdx.x + 1] = red[0];
}

__global__ void finalize_kernel(const float* __restrict__ partials, int nblocks,
                                float* __restrict__ out_loss, int write_float)
{
    if (threadIdx.x == 0 && write_float) {
        float s = 0.f, v = 0.f;
        for (int i = 0; i < nblocks; i++) { s += partials[2*i]; v += partials[2*i+1]; }
        out_loss[0] = s / fmaxf(v, 1.0f);
    }
}

// ---------------------------- host driver -----------------------------------
extern "C" void kernel_launch(void* const* d_in, const int* in_sizes, int n_in,
                              void* d_out, int out_size)
{
    const float* enc   = (const float*)d_in[0];
    const float* desc  = (const float*)d_in[1];
    const int*   maskA = (const int*)  d_in[2];
    const int*   cand  = (const int*)  d_in[3];
    const int*   labels= (const int*)  d_in[4];
    const float* ipw   = (const float*)d_in[5];   // (L, 3E, E)
    const float* ipb   = (const float*)d_in[6];   // (L, 3E)
    const float* outw  = (const float*)d_in[7];   // (L, E, E)
    const float* outb  = (const float*)d_in[8];   // (L, E)
    const float* ln1g  = (const float*)d_in[9];
    const float* ln1b  = (const float*)d_in[10];
    const float* fw1   = (const float*)d_in[11];  // (L, F, E)
    const float* fb1   = (const float*)d_in[12];  // (L, F)
    const float* fw2   = (const float*)d_in[13];  // (L, E, F)
    const float* fb2   = (const float*)d_in[14];  // (L, E)
    const float* ln2g  = (const float*)d_in[15];
    const float* ln2b  = (const float*)d_in[16];
    const float* clsw  = (const float*)d_in[17];  // (C, E)
    const float* clsb  = (const float*)d_in[18];  // (C,)

    float *pA, *pQ, *pK, *pV, *pC, *pO, *pA1, *pS, *pH, *pPart;
    cudaGetSymbolAddress((void**)&pA,  g_bufA);
    cudaGetSymbolAddress((void**)&pQ,  g_bufQ);
    cudaGetSymbolAddress((void**)&pK,  g_bufK);
    cudaGetSymbolAddress((void**)&pV,  g_bufV);
    cudaGetSymbolAddress((void**)&pC,  g_bufC);
    cudaGetSymbolAddress((void**)&pO,  g_bufO);
    cudaGetSymbolAddress((void**)&pA1, g_bufA1);
    cudaGetSymbolAddress((void**)&pS,  g_bufS);
    cudaGetSymbolAddress((void**)&pH,  g_bufH);
    cudaGetSymbolAddress((void**)&pPart, g_partials);

    // zero out output (poisoned with 0xAA by harness)
    cudaMemsetAsync(d_out, 0, (size_t)out_size * sizeof(float));

    // A <- encoded_matrix
    cudaMemcpyAsync(pA, enc, (size_t)NTOK * EDIM * sizeof(float),
                    cudaMemcpyDeviceToDevice);

    const dim3 gemm_tb(256);
    const dim3 g_proj(EDIM / 128, NTOK / 128);         // (8, 32)
    const dim3 g_ffn1(FFD / 128, NTOK / 128);          // (32, 32)
    const dim3 g_sc(SBK / 64, SAQ / 64, BB * HH);      // (8, 8, 128)
    const dim3 g_ctx(1, SAQ / 64, BB * HH);            // (1, 8, 128)

    for (int l = 0; l < LL; l++) {
        const float* wq = ipw + (size_t)l * 3 * EDIM * EDIM;
        const float* wk = wq + (size_t)EDIM * EDIM;
        const float* wv = wk + (size_t)EDIM * EDIM;
        const float* bq = ipb + (size_t)l * 3 * EDIM;
        const float* bk = bq + EDIM;
        const float* bv = bk + EDIM;

        sgemm_nt_kernel<<<g_proj, gemm_tb>>>(pA,   wq, bq, pQ, NTOK, EDIM, EDIM, 0);
        sgemm_nt_kernel<<<g_proj, gemm_tb>>>(desc, wk, bk, pK, NTOK, EDIM, EDIM, 0);
        sgemm_nt_kernel<<<g_proj, gemm_tb>>>(desc, wv, bv, pV, NTOK, EDIM, EDIM, 0);

        attn_scores_kernel<<<g_sc, 256>>>(pQ, pK, pS);
        softmax_kernel<<<BB * HH * SAQ, 128>>>(pS);
        attn_ctx_kernel<<<g_ctx, 256>>>(pS, pV, pC);

        sgemm_nt_kernel<<<g_proj, gemm_tb>>>(pC, outw + (size_t)l * EDIM * EDIM,
                                             outb + (size_t)l * EDIM, pO,
                                             NTOK, EDIM, EDIM, 0);

        ln_residual_kernel<<<NTOK, 256>>>(pA, pO, ln1g + (size_t)l * EDIM,
                                          ln1b + (size_t)l * EDIM, pA1);

        sgemm_nt_kernel<<<g_ffn1, gemm_tb>>>(pA1, fw1 + (size_t)l * FFD * EDIM,
                                             fb1 + (size_t)l * FFD, pH,
                                             NTOK, FFD, EDIM, 1);
        sgemm_nt_kernel<<<g_proj, gemm_tb>>>(pH, fw2 + (size_t)l * EDIM * FFD,
                                             fb2 + (size_t)l * EDIM, pO,
                                             NTOK, EDIM, FFD, 0);

        ln_residual_kernel<<<NTOK, 256>>>(pA1, pO, ln2g + (size_t)l * EDIM,
                                          ln2b + (size_t)l * EDIM, pA);
    }

    // Output layout guess: out_size == 1 + NTOK floats -> [loss, labels...]
    int write_float = (out_size > NTOK) ? 1 : 0;
    int lab_off = write_float ? (out_size - NTOK) : 0;
    float* outf = (float*)d_out;
    int*   outi = (int*)d_out;

    cls_kernel<<<NTOK / 128, 128>>>(pA, clsw, clsb, maskA, cand, labels,
                                    outf + lab_off, outi, write_float, pPart);
    finalize_kernel<<<1, 32>>>(pPart, NTOK / 128, outf, write_float);
}

// round 5
// speedup vs baseline: 1.0556x; 1.0556x over previous
#include <cuda_runtime.h>
#include <math.h>
#include <stdint.h>

// Problem constants
#define BB    8
#define SAQ   512
#define SBK   512
#define EDIM  1024
#define HH    16
#define DH    64
#define FFD   4096
#define LL    9
#define NTOK  (BB*SAQ)          // 4096 rows
#define WEIGHTV 5.0f
#define EPSV    1e-5f
#define ATT_SCALE 0.125f        // 1/sqrt(64)

// ---------------- scratch (device globals; no allocation allowed) ------------
__device__ float g_bufA [NTOK*EDIM];
__device__ float g_bufQ [NTOK*EDIM];
__device__ float g_bufK [NTOK*EDIM];
__device__ float g_bufV [NTOK*EDIM];
__device__ float g_bufC [NTOK*EDIM];
__device__ float g_bufO [NTOK*EDIM];
__device__ float g_bufA1[NTOK*EDIM];
__device__ float g_bufS [(size_t)BB*HH*SAQ*SBK];   // 33.5M floats
__device__ float g_bufH [(size_t)NTOK*FFD];        // 16.7M floats
__device__ float g_partials[64];                   // 32 blocks x (wce, valid)

// -------- packed f32x2 helpers (Blackwell dual-FP32; base sm_100+ PTX) -------
// FMA2: acc.lo += a.lo*b.lo ; acc.hi += a.hi*b.hi
#define FMA2(acc, a, b) \
    asm("fma.rn.f32x2 %0, %1, %2, %0;" : "+l"(acc) : "l"(a), "l"(b))
// PACK2: d = (s, s) broadcast (s is fp32 bits in a u32 reg)
#define PACK2(d, s) \
    asm("mov.b64 %0, {%1, %1};" : "=l"(d) : "r"(s))
// UNPACK2: (lo, hi) <- v
#define UNPACK2(lo, hi, v) \
    asm("mov.b64 {%0, %1}, %2;" : "=r"(lo), "=r"(hi) : "l"(v))

// ---------------- SGEMM: C[M,N] = A[M,K] @ W[N,K]^T + bias[N], opt relu -----
// Requires M%128==0, N%128==0, K%16==0 (true for all calls here).
// Inner product uses packed FFMA2: 8 rows x 4 col-pairs per thread.
__global__ void __launch_bounds__(256, 2)
sgemm_nt_kernel(const float* __restrict__ A, const float* __restrict__ W,
                const float* __restrict__ bias, float* __restrict__ C,
                int M, int N, int K, int relu)
{
    const int bx = blockIdx.x;          // N tile
    const int by = blockIdx.y;          // M tile
    const int tid = threadIdx.x;
    const int tx = tid & 15;            // 0..15 -> cols
    const int ty = tid >> 4;            // 0..15 -> rows

    __shared__ float As[16][128];
    __shared__ float Bs[16][128];

    unsigned long long acc2[8][4];
#pragma unroll
    for (int i = 0; i < 8; i++)
#pragma unroll
        for (int j = 0; j < 4; j++) acc2[i][j] = 0ull;

    const float* Ab = A + (size_t)(by * 128) * K;
    const float* Wb = W + (size_t)(bx * 128) * K;

    for (int kt = 0; kt < K; kt += 16) {
#pragma unroll
        for (int i = 0; i < 2; i++) {
            int f   = tid + i * 256;        // 0..511
            int row = f >> 2;               // 0..127
            int kq  = (f & 3) << 2;         // 0,4,8,12
            float4 a = *(const float4*)(Ab + (size_t)row * K + kt + kq);
            As[kq+0][row] = a.x; As[kq+1][row] = a.y;
            As[kq+2][row] = a.z; As[kq+3][row] = a.w;
            float4 b = *(const float4*)(Wb + (size_t)row * K + kt + kq);
            Bs[kq+0][row] = b.x; Bs[kq+1][row] = b.y;
            Bs[kq+2][row] = b.z; Bs[kq+3][row] = b.w;
        }
        __syncthreads();

#pragma unroll
        for (int kk = 0; kk < 16; kk++) {
            uint4 a0 = *(const uint4*)&As[kk][ty*4];
            uint4 a1 = *(const uint4*)&As[kk][64 + ty*4];
            ulonglong2 b0 = *(const ulonglong2*)&Bs[kk][tx*4];
            ulonglong2 b1 = *(const ulonglong2*)&Bs[kk][64 + tx*4];
            unsigned long long ap[8];
            PACK2(ap[0], a0.x); PACK2(ap[1], a0.y);
            PACK2(ap[2], a0.z); PACK2(ap[3], a0.w);
            PACK2(ap[4], a1.x); PACK2(ap[5], a1.y);
            PACK2(ap[6], a1.z); PACK2(ap[7], a1.w);
#pragma unroll
            for (int i = 0; i < 8; i++) {
                FMA2(acc2[i][0], ap[i], b0.x);
                FMA2(acc2[i][1], ap[i], b0.y);
                FMA2(acc2[i][2], ap[i], b1.x);
                FMA2(acc2[i][3], ap[i], b1.y);
            }
        }
        __syncthreads();
    }

    // epilogue
#pragma unroll
    for (int ih = 0; ih < 2; ih++) {
#pragma unroll
        for (int i = 0; i < 4; i++) {
            int r = by * 128 + ih * 64 + ty * 4 + i;
            int irow = ih * 4 + i;
            float* crow = C + (size_t)r * N + bx * 128;
#pragma unroll
            for (int jh = 0; jh < 2; jh++) {
                int c = jh * 64 + tx * 4;
                float4 bv = *(const float4*)(bias + bx * 128 + c);
                uint32_t l0, h0, l1, h1;
                UNPACK2(l0, h0, acc2[irow][jh*2+0]);
                UNPACK2(l1, h1, acc2[irow][jh*2+1]);
                float4 v;
                v.x = __uint_as_float(l0) + bv.x;
                v.y = __uint_as_float(h0) + bv.y;
                v.z = __uint_as_float(l1) + bv.z;
                v.w = __uint_as_float(h1) + bv.w;
                if (relu) {
                    v.x = fmaxf(v.x, 0.f); v.y = fmaxf(v.y, 0.f);
                    v.z = fmaxf(v.z, 0.f); v.w = fmaxf(v.w, 0.f);
                }
                *(float4*)(crow + c) = v;
            }
        }
    }
}

// ---------------- attention scores: S[b,h,q,k] = scale * Q.Kh^T -------------
__global__ void __launch_bounds__(256)
attn_scores_kernel(const float* __restrict__ Q, const float* __restrict__ Km,
                   float* __restrict__ S)
{
    int z = blockIdx.z;                 // b*H + h
    int b = z >> 4, h = z & 15;
    const float* Qp = Q + (size_t)b * SAQ * EDIM + h * DH;
    const float* Kp = Km + (size_t)b * SBK * EDIM + h * DH;
    float* Sp = S + (size_t)z * SAQ * SBK;
    int q0 = blockIdx.y * 64, k0 = blockIdx.x * 64;
    int tid = threadIdx.x, tx = tid & 15, ty = tid >> 4;

    __shared__ float Qs[64][64];  // [d][q]
    __shared__ float Ks[64][64];  // [d][k]

#pragma unroll
    for (int i = 0; i < 4; i++) {
        int f = tid + i * 256;          // 0..1023
        int row = f >> 4;               // 0..63
        int dq  = (f & 15) << 2;        // 0..60
        float4 a = *(const float4*)(Qp + (size_t)(q0 + row) * EDIM + dq);
        Qs[dq+0][row] = a.x; Qs[dq+1][row] = a.y;
        Qs[dq+2][row] = a.z; Qs[dq+3][row] = a.w;
        float4 k = *(const float4*)(Kp + (size_t)(k0 + row) * EDIM + dq);
        Ks[dq+0][row] = k.x; Ks[dq+1][row] = k.y;
        Ks[dq+2][row] = k.z; Ks[dq+3][row] = k.w;
    }
    __syncthreads();

    unsigned long long acc2[4][2];
#pragma unroll
    for (int i = 0; i < 4; i++) { acc2[i][0] = 0ull; acc2[i][1] = 0ull; }

#pragma unroll
    for (int d = 0; d < 64; d++) {
        uint4 a = *(const uint4*)&Qs[d][ty*4];
        ulonglong2 b2 = *(const ulonglong2*)&Ks[d][tx*4];
        unsigned long long ap[4];
        PACK2(ap[0], a.x); PACK2(ap[1], a.y);
        PACK2(ap[2], a.z); PACK2(ap[3], a.w);
#pragma unroll
        for (int i = 0; i < 4; i++) {
            FMA2(acc2[i][0], ap[i], b2.x);
            FMA2(acc2[i][1], ap[i], b2.y);
        }
    }

#pragma unroll
    for (int i = 0; i < 4; i++) {
        uint32_t l0, h0, l1, h1;
        UNPACK2(l0, h0, acc2[i][0]);
        UNPACK2(l1, h1, acc2[i][1]);
        float4 v;
        v.x = __uint_as_float(l0) * ATT_SCALE;
        v.y = __uint_as_float(h0) * ATT_SCALE;
        v.z = __uint_as_float(l1) * ATT_SCALE;
        v.w = __uint_as_float(h1) * ATT_SCALE;
        *(float4*)(Sp + (size_t)(q0 + ty*4 + i) * SBK + k0 + tx*4) = v;
    }
}

// ---------------- row softmax over last dim (512) ---------------------------
__global__ void __launch_bounds__(128)
softmax_kernel(float* __restrict__ S)
{
    size_t row = blockIdx.x;
    float* p = S + row * SBK;
    int tid = threadIdx.x;
    __shared__ float sbuf[4];

    float4 v = ((float4*)p)[tid];
    float m = fmaxf(fmaxf(v.x, v.y), fmaxf(v.z, v.w));
#pragma unroll
    for (int o = 16; o > 0; o >>= 1) m = fmaxf(m, __shfl_xor_sync(0xffffffffu, m, o));
    if ((tid & 31) == 0) sbuf[tid >> 5] = m;
    __syncthreads();
    m = fmaxf(fmaxf(sbuf[0], sbuf[1]), fmaxf(sbuf[2], sbuf[3]));
    __syncthreads();

    float4 e;
    e.x = expf(v.x - m); e.y = expf(v.y - m);
    e.z = expf(v.z - m); e.w = expf(v.w - m);
    float s = e.x + e.y + e.z + e.w;
#pragma unroll
    for (int o = 16; o > 0; o >>= 1) s += __shfl_xor_sync(0xffffffffu, s, o);
    if ((tid & 31) == 0) sbuf[tid >> 5] = s;
    __syncthreads();
    s = sbuf[0] + sbuf[1] + sbuf[2] + sbuf[3];
    float inv = 1.0f / s;
    e.x *= inv; e.y *= inv; e.z *= inv; e.w *= inv;
    ((float4*)p)[tid] = e;
}

// ---------------- ctx[b,q,h*64+d] = sum_k P[z,q,k] * V[b,k,h*64+d] ----------
__global__ void __launch_bounds__(256)
attn_ctx_kernel(const float* __restrict__ P, const float* __restrict__ V,
                float* __restrict__ Ctx)
{
    int z = blockIdx.z;
    int b = z >> 4, h = z & 15;
    const float* Pp = P + (size_t)z * SAQ * SBK;
    const float* Vp = V + (size_t)b * SBK * EDIM + h * DH;
    float* Cp = Ctx + (size_t)b * SAQ * EDIM + h * DH;
    int q0 = blockIdx.y * 64;
    int tid = threadIdx.x, tx = tid & 15, ty = tid >> 4;

    __shared__ float Ps[32][64];  // [k][q]
    __shared__ float Vs[32][64];  // [k][d]

    unsigned long long acc2[4][2];
#pragma unroll
    for (int i = 0; i < 4; i++) { acc2[i][0] = 0ull; acc2[i][1] = 0ull; }

    for (int kt = 0; kt < SBK; kt += 32) {
#pragma unroll
        for (int i = 0; i < 2; i++) {
            int f = tid + i * 256;        // 0..511
            {   // P tile: 64 q rows x 32 k cols
                int row = f >> 3;         // 0..63
                int kq  = (f & 7) << 2;   // 0..28
                float4 p = *(const float4*)(Pp + (size_t)(q0 + row) * SBK + kt + kq);
                Ps[kq+0][row] = p.x; Ps[kq+1][row] = p.y;
                Ps[kq+2][row] = p.z; Ps[kq+3][row] = p.w;
            }
            {   // V tile: 32 k rows x 64 d cols
                int row = f >> 4;         // 0..31
                int dq  = (f & 15) << 2;  // 0..60
                float4 vv = *(const float4*)(Vp + (size_t)(kt + row) * EDIM + dq);
                *(float4*)&Vs[row][dq] = vv;
            }
        }
        __syncthreads();

#pragma unroll
        for (int kk = 0; kk < 32; kk++) {
            uint4 a = *(const uint4*)&Ps[kk][ty*4];
            ulonglong2 b2 = *(const ulonglong2*)&Vs[kk][tx*4];
            unsigned long long ap[4];
            PACK2(ap[0], a.x); PACK2(ap[1], a.y);
            PACK2(ap[2], a.z); PACK2(ap[3], a.w);
#pragma unroll
            for (int i = 0; i < 4; i++) {
                FMA2(acc2[i][0], ap[i], b2.x);
                FMA2(acc2[i][1], ap[i], b2.y);
            }
        }
        __syncthreads();
    }

#pragma unroll
    for (int i = 0; i < 4; i++) {
        uint32_t l0, h0, l1, h1;
        UNPACK2(l0, h0, acc2[i][0]);
        UNPACK2(l1, h1, acc2[i][1]);
        float4 v;
        v.x = __uint_as_float(l0); v.y = __uint_as_float(h0);
        v.z = __uint_as_float(l1); v.w = __uint_as_float(h1);
        *(float4*)(Cp + (size_t)(q0 + ty*4 + i) * EDIM + tx*4) = v;
    }
}

// ---------------- LayerNorm(residual): Y = LN(X + R) * g + b ----------------
__global__ void __launch_bounds__(256)
ln_residual_kernel(const float* __restrict__ X, const float* __restrict__ R,
                   const float* __restrict__ g, const float* __restrict__ bta,
                   float* __restrict__ Y)
{
    int row = blockIdx.x;
    int tid = threadIdx.x;                // 256 threads, 4 floats each
    __shared__ float sbuf[8];

    float4 x = ((const float4*)(X + (size_t)row * EDIM))[tid];
    float4 r = ((const float4*)(R + (size_t)row * EDIM))[tid];
    float4 v;
    v.x = x.x + r.x; v.y = x.y + r.y; v.z = x.z + r.z; v.w = x.w + r.w;

    float s = v.x + v.y + v.z + v.w;
#pragma unroll
    for (int o = 16; o > 0; o >>= 1) s += __shfl_xor_sync(0xffffffffu, s, o);
    if ((tid & 31) == 0) sbuf[tid >> 5] = s;
    __syncthreads();
    if (tid < 32) {
        float t = (tid < 8) ? sbuf[tid] : 0.f;
#pragma unroll
        for (int o = 4; o > 0; o >>= 1) t += __shfl_xor_sync(0xffffffffu, t, o);
        if (tid == 0) sbuf[0] = t;
    }
    __syncthreads();
    float mean = sbuf[0] * (1.0f / EDIM);
    __syncthreads();

    float4 d;
    d.x = v.x - mean; d.y = v.y - mean; d.z = v.z - mean; d.w = v.w - mean;
    float sq = d.x*d.x + d.y*d.y + d.z*d.z + d.w*d.w;
#pragma unroll
    for (int o = 16; o > 0; o >>= 1) sq += __shfl_xor_sync(0xffffffffu, sq, o);
    if ((tid & 31) == 0) sbuf[tid >> 5] = sq;
    __syncthreads();
    if (tid < 32) {
        float t = (tid < 8) ? sbuf[tid] : 0.f;
#pragma unroll
        for (int o = 4; o > 0; o >>= 1) t += __shfl_xor_sync(0xffffffffu, t, o);
        if (tid == 0) sbuf[0] = t;
    }
    __syncthreads();
    float var = sbuf[0] * (1.0f / EDIM);
    float inv = rsqrtf(var + EPSV);

    float4 gg = ((const float4*)g)[tid];
    float4 bb = ((const float4*)bta)[tid];
    float4 o4;
    o4.x = d.x * inv * gg.x + bb.x;
    o4.y = d.y * inv * gg.y + bb.y;
    o4.z = d.z * inv * gg.z + bb.z;
    o4.w = d.w * inv * gg.w + bb.w;
    ((float4*)(Y + (size_t)row * EDIM))[tid] = o4;
}

// ---------------- classifier + per-row loss + predicted labels --------------
__global__ void __launch_bounds__(128)
cls_kernel(const float* __restrict__ A, const float* __restrict__ cw,
           const float* __restrict__ cb, const int* __restrict__ mask,
           const int* __restrict__ cand, const int* __restrict__ labels,
           float* __restrict__ out_lab_f, int* __restrict__ out_lab_i,
           int write_float, float* __restrict__ partials)
{
    __shared__ float w0[EDIM];
    __shared__ float w1[EDIM];
    __shared__ float red[128];
    int tid = threadIdx.x;
#pragma unroll
    for (int i = 0; i < EDIM / 128; i++) {
        w0[tid + i * 128] = cw[tid + i * 128];
        w1[tid + i * 128] = cw[EDIM + tid + i * 128];
    }
    __syncthreads();

    int row = blockIdx.x * 128 + tid;     // 0..4095
    const float* a = A + (size_t)row * EDIM;
    float e0 = cb[0], e1 = cb[1];
#pragma unroll 4
    for (int i = 0; i < EDIM; i += 4) {
        float4 av = *(const float4*)(a + i);
        e0 += av.x * w0[i] + av.y * w0[i+1] + av.z * w0[i+2] + av.w * w0[i+3];
        e1 += av.x * w1[i] + av.y * w1[i+1] + av.z * w1[i+2] + av.w * w1[i+3];
    }
    int lab = labels[row];
    float m = fmaxf(e0, e1);
    float lse = m + logf(expf(e0 - m) + expf(e1 - m));
    float logp = ((lab == 1) ? e1 : e0) - lse;
    float ce = -logp;
    float w = (lab == 1) ? WEIGHTV : 1.0f;
    float valid = (mask[row] == 1) ? 1.0f : 0.0f;
    float contrib = ce * w * valid;

    int pred = (e1 > e0) ? 1 : 0;        // jnp.argmax: ties -> 0
    int pl = (cand[row] == 1 && pred == 1) ? 1 : 0;
    if (write_float) out_lab_f[row] = (float)pl;
    else             out_lab_i[row] = pl;

    // deterministic block reduce of (contrib, valid)
    red[tid] = contrib;
    __syncthreads();
    for (int o = 64; o > 0; o >>= 1) {
        if (tid < o) red[tid] += red[tid + o];
        __syncthreads();
    }
    if (tid == 0) partials[2 * blockIdx.x] = red[0];
    __syncthreads();
    red[tid] = valid;
    __syncthreads();
    for (int o = 64; o > 0; o >>= 1) {
        if (tid < o) red[tid] += red[tid + o];
        __syncthreads();
    }
    if (tid == 0) partials[2 * blockIdx.x + 1] = red[0];
}

__global__ void finalize_kernel(const float* __restrict__ partials, int nblocks,
                                float* __restrict__ out_loss, int write_float)
{
    if (threadIdx.x == 0 && write_float) {
        float s = 0.f, v = 0.f;
        for (int i = 0; i < nblocks; i++) { s += partials[2*i]; v += partials[2*i+1]; }
        out_loss[0] = s / fmaxf(v, 1.0f);
    }
}

// ---------------------------- host driver -----------------------------------
extern "C" void kernel_launch(void* const* d_in, const int* in_sizes, int n_in,
                              void* d_out, int out_size)
{
    const float* enc   = (const float*)d_in[0];
    const float* desc  = (const float*)d_in[1];
    const int*   maskA = (const int*)  d_in[2];
    const int*   cand  = (const int*)  d_in[3];
    const int*   labels= (const int*)  d_in[4];
    const float* ipw   = (const float*)d_in[5];   // (L, 3E, E)
    const float* ipb   = (const float*)d_in[6];   // (L, 3E)
    const float* outw  = (const float*)d_in[7];   // (L, E, E)
    const float* outb  = (const float*)d_in[8];   // (L, E)
    const float* ln1g  = (const float*)d_in[9];
    const float* ln1b  = (const float*)d_in[10];
    const float* fw1   = (const float*)d_in[11];  // (L, F, E)
    const float* fb1   = (const float*)d_in[12];  // (L, F)
    const float* fw2   = (const float*)d_in[13];  // (L, E, F)
    const float* fb2   = (const float*)d_in[14];  // (L, E)
    const float* ln2g  = (const float*)d_in[15];
    const float* ln2b  = (const float*)d_in[16];
    const float* clsw  = (const float*)d_in[17];  // (C, E)
    const float* clsb  = (const float*)d_in[18];  // (C,)

    float *pA, *pQ, *pK, *pV, *pC, *pO, *pA1, *pS, *pH, *pPart;
    cudaGetSymbolAddress((void**)&pA,  g_bufA);
    cudaGetSymbolAddress((void**)&pQ,  g_bufQ);
    cudaGetSymbolAddress((void**)&pK,  g_bufK);
    cudaGetSymbolAddress((void**)&pV,  g_bufV);
    cudaGetSymbolAddress((void**)&pC,  g_bufC);
    cudaGetSymbolAddress((void**)&pO,  g_bufO);
    cudaGetSymbolAddress((void**)&pA1, g_bufA1);
    cudaGetSymbolAddress((void**)&pS,  g_bufS);
    cudaGetSymbolAddress((void**)&pH,  g_bufH);
    cudaGetSymbolAddress((void**)&pPart, g_partials);

    // zero out output (poisoned with 0xAA by harness)
    cudaMemsetAsync(d_out, 0, (size_t)out_size * sizeof(float));

    // A <- encoded_matrix
    cudaMemcpyAsync(pA, enc, (size_t)NTOK * EDIM * sizeof(float),
                    cudaMemcpyDeviceToDevice);

    const dim3 gemm_tb(256);
    const dim3 g_proj(EDIM / 128, NTOK / 128);         // (8, 32)
    const dim3 g_ffn1(FFD / 128, NTOK / 128);          // (32, 32)
    const dim3 g_sc(SBK / 64, SAQ / 64, BB * HH);      // (8, 8, 128)
    const dim3 g_ctx(1, SAQ / 64, BB * HH);            // (1, 8, 128)

    for (int l = 0; l < LL; l++) {
        const float* wq = ipw + (size_t)l * 3 * EDIM * EDIM;
        const float* wk = wq + (size_t)EDIM * EDIM;
        const float* wv = wk + (size_t)EDIM * EDIM;
        const float* bq = ipb + (size_t)l * 3 * EDIM;
        const float* bk = bq + EDIM;
        const float* bv = bk + EDIM;

        sgemm_nt_kernel<<<g_proj, gemm_tb>>>(pA,   wq, bq, pQ, NTOK, EDIM, EDIM, 0);
        sgemm_nt_kernel<<<g_proj, gemm_tb>>>(desc, wk, bk, pK, NTOK, EDIM, EDIM, 0);
        sgemm_nt_kernel<<<g_proj, gemm_tb>>>(desc, wv, bv, pV, NTOK, EDIM, EDIM, 0);

        attn_scores_kernel<<<g_sc, 256>>>(pQ, pK, pS);
        softmax_kernel<<<BB * HH * SAQ, 128>>>(pS);
        attn_ctx_kernel<<<g_ctx, 256>>>(pS, pV, pC);

        sgemm_nt_kernel<<<g_proj, gemm_tb>>>(pC, outw + (size_t)l * EDIM * EDIM,
                                             outb + (size_t)l * EDIM, pO,
                                             NTOK, EDIM, EDIM, 0);

        ln_residual_kernel<<<NTOK, 256>>>(pA, pO, ln1g + (size_t)l * EDIM,
                                          ln1b + (size_t)l * EDIM, pA1);

        sgemm_nt_kernel<<<g_ffn1, gemm_tb>>>(pA1, fw1 + (size_t)l * FFD * EDIM,
                                             fb1 + (size_t)l * FFD, pH,
                                             NTOK, FFD, EDIM, 1);
        sgemm_nt_kernel<<<g_proj, gemm_tb>>>(pH, fw2 + (size_t)l * EDIM * FFD,
                                             fb2 + (size_t)l * EDIM, pO,
                                             NTOK, EDIM, FFD, 0);

        ln_residual_kernel<<<NTOK, 256>>>(pA1, pO, ln2g + (size_t)l * EDIM,
                                          ln2b + (size_t)l * EDIM, pA);
    }

    int write_float = (out_size > NTOK) ? 1 : 0;
    int lab_off = write_float ? (out_size - NTOK) : 0;
    float* outf = (float*)d_out;
    int*   outi = (int*)d_out;

    cls_kernel<<<NTOK / 128, 128>>>(pA, clsw, clsb, maskA, cand, labels,
                                    outf + lab_off, outi, write_float, pPart);
    finalize_kernel<<<1, 32>>>(pPart, NTOK / 128, outf, write_float);
}